// round 1
// baseline (speedup 1.0000x reference)
#include <cuda_runtime.h>

#define BB 4
#define CI 256
#define CO 128
#define HH 56
#define WW 56
#define KK 49

// scratch (static device allocations are allowed)
__device__ float g_O1[BB*CO*HH*WW];          // conv1 output, 6.4 MB
__device__ float g_Wt[CI*KK*CO];             // W1 transposed: [(c*49+t)][m]

// ---------------- kernel 0: transpose W1 [m][c*49+t] -> [c*49+t][m] -------
__global__ void k_transpose(const float* __restrict__ W1) {
    int idx = blockIdx.x * 256 + threadIdx.x;      // over CI*KK*CO
    if (idx >= CI*KK*CO) return;
    int m  = idx & (CO - 1);
    int ct = idx >> 7;
    g_Wt[idx] = W1[m * (CI*KK) + ct];
}

// ---------------- kernel 1: conv1 7x7 dil2 pad6 + bias --------------------
// Block: 32 out-channels x 2 rows x 56 cols. Threads 224 = 8(tc) x 2(tpy) x 14(tpx)
// Thread tile: 4 ch x 4 px. c-chunks of 4 staged in smem.
#define CC 4
#define MG 32
#define XWID 72   // smem x row width: global cols -6..65 (col = gx+6)

__global__ void __launch_bounds__(224) k_conv1(const float* __restrict__ x,
                                               const float* __restrict__ b1) {
    __shared__ float Xs[CC][14][XWID];     // 16128 B
    __shared__ float Ws[CC][KK][MG];       // 25088 B

    int tid = threadIdx.x;
    int tc  = tid / 28;            // 0..7
    int tpy = (tid % 28) / 14;     // 0..1
    int tpx = tid % 14;            // 0..13

    int rp = blockIdx.x;           // 0..27  row pair
    int mg = blockIdx.y;           // 0..3   channel group of 32
    int b  = blockIdx.z;

    int y0  = rp * 2;
    int y   = y0 + tpy;
    int px0 = tpx * 4;
    int m0  = mg * MG;
    int mt  = m0 + tc * 4;

    float acc[4][4];
    #pragma unroll
    for (int a = 0; a < 4; a++)
        #pragma unroll
        for (int d = 0; d < 4; d++) acc[a][d] = 0.f;

    const float* xb = x + (size_t)b * CI * HH * WW;

    for (int cb = 0; cb < CI; cb += CC) {
        __syncthreads();
        // ---- stage X: CC * 14 rows * 34 float2 slots (col = gx+6, gx = 2*s2-6)
        for (int s = tid; s < CC * 14 * 34; s += 224) {
            int c  = s / (14 * 34);
            int rr = (s / 34) % 14;
            int s2 = s % 34;
            int gx = 2 * s2 - 6;
            int gy = y0 - 6 + rr;
            float2 v = make_float2(0.f, 0.f);
            if (gy >= 0 && gy < HH && gx >= 0 && gx < WW) {
                v = *reinterpret_cast<const float2*>(
                        xb + (size_t)(cb + c) * HH * WW + gy * WW + gx);
            }
            *reinterpret_cast<float2*>(&Xs[c][rr][2 * s2]) = v;
        }
        // ---- stage W: CC*49*32 floats as float4, coalesced from g_Wt
        for (int s = tid; s < (CC * KK * MG) / 4; s += 224) {
            int lin = s * 4;
            int c   = lin / (KK * MG);
            int rem = lin % (KK * MG);
            int t   = rem / MG;
            int m   = rem % MG;
            float4 v = *reinterpret_cast<const float4*>(
                &g_Wt[(size_t)((cb + c) * KK + t) * CO + m0 + m]);
            *reinterpret_cast<float4*>(&Ws[c][t][m]) = v;
        }
        __syncthreads();

        for (int c = 0; c < CC; c++) {
            for (int i = 0; i < 7; i++) {
                int rr = tpy + 2 * i;
                float xv[16];
                #pragma unroll
                for (int q = 0; q < 4; q++) {
                    float4 t4 = *reinterpret_cast<const float4*>(&Xs[c][rr][px0 + 4 * q]);
                    xv[4*q+0] = t4.x; xv[4*q+1] = t4.y;
                    xv[4*q+2] = t4.z; xv[4*q+3] = t4.w;
                }
                #pragma unroll
                for (int j = 0; j < 7; j++) {
                    float4 wv = *reinterpret_cast<const float4*>(&Ws[c][7*i+j][tc*4]);
                    float w[4] = {wv.x, wv.y, wv.z, wv.w};
                    #pragma unroll
                    for (int a = 0; a < 4; a++)
                        #pragma unroll
                        for (int d = 0; d < 4; d++)
                            acc[a][d] += w[a] * xv[2*j + d];
                }
            }
        }
    }

    #pragma unroll
    for (int a = 0; a < 4; a++) {
        float bias = b1[mt + a];
        float4 o;
        o.x = acc[a][0] + bias; o.y = acc[a][1] + bias;
        o.z = acc[a][2] + bias; o.w = acc[a][3] + bias;
        *reinterpret_cast<float4*>(
            &g_O1[(size_t)(((b * CO + mt + a) * HH) + y) * WW + px0]) = o;
    }
}

// ---------------- kernel 2: 1x1 conv -> softmax(49) -> weighted patch sum --
// Block per (b, row y). 224 threads.
// dyn smem: ls[49*56] | region aliased: {O1s[128*56], W2s[49*128]} then xs[32*7*72]
#define S2_LS   (49 * 56)
#define S2_XS   (32 * 7 * 72)
#define S2_SMEM ((S2_LS + S2_XS) * 4)

__global__ void __launch_bounds__(224) k_stage2(const float* __restrict__ x,
                                                const float* __restrict__ W2,
                                                const float* __restrict__ b2,
                                                float* __restrict__ out) {
    extern __shared__ float sm[];
    float* ls  = sm;               // persists whole kernel
    float* O1s = sm + S2_LS;       // phase A only
    float* W2s = O1s + CO * WW;    // phase A only  (O1s+W2s = 13440 fl < 16128)
    float* xs  = sm + S2_LS;       // phase B, aliases O1s/W2s

    int tid = threadIdx.x;
    int y = blockIdx.x;
    int b = blockIdx.y;

    // ---- phase A: load O1 row + W2
    for (int s = tid; s < CO * 14; s += 224) {
        int c = s / 14, q = s % 14;
        float4 v = *reinterpret_cast<const float4*>(
            &g_O1[(size_t)((b * CO + c) * HH + y) * WW + 4 * q]);
        *reinterpret_cast<float4*>(&O1s[c * WW + 4 * q]) = v;
    }
    for (int s = tid; s < (KK * CO) / 4; s += 224) {
        *reinterpret_cast<float4*>(&W2s[4 * s]) =
            *reinterpret_cast<const float4*>(&W2[4 * s]);
    }
    __syncthreads();

    // logits: ls[k][x] = b2[k] + sum_c W2[k][c] * O1[c][x]
    for (int p = tid; p < KK * WW; p += 224) {
        int k = p / WW, xc = p % WW;
        float acc = b2[k];
        #pragma unroll 8
        for (int c = 0; c < CO; c++)
            acc += W2s[k * CO + c] * O1s[c * WW + xc];
        ls[k * WW + xc] = acc;
    }
    __syncthreads();

    // softmax over k (one thread per column)
    if (tid < WW) {
        float mx = -1e30f;
        #pragma unroll
        for (int k = 0; k < KK; k++) mx = fmaxf(mx, ls[k * WW + tid]);
        float s = 0.f;
        #pragma unroll
        for (int k = 0; k < KK; k++) {
            float e = expf(ls[k * WW + tid] - mx);
            ls[k * WW + tid] = e;
            s += e;
        }
        float inv = 1.f / s;
        #pragma unroll
        for (int k = 0; k < KK; k++) ls[k * WW + tid] *= inv;
    }
    __syncthreads();

    // hoist attn to registers
    int cl = tid / WW;     // 0..3
    int xc = tid % WW;     // 0..55
    float av[KK];
    #pragma unroll
    for (int k = 0; k < KK; k++) av[k] = ls[k * WW + xc];

    // ---- phase B: weighted local sum, 8 chunks of 32 channels
    for (int cc = 0; cc < CI / 32; cc++) {
        __syncthreads();
        for (int s = tid; s < 32 * 7 * 34; s += 224) {
            int c  = s / (7 * 34);
            int i  = (s / 34) % 7;
            int s2 = s % 34;
            int gx = 2 * s2 - 6;
            int gy = y - 6 + 2 * i;
            float2 v = make_float2(0.f, 0.f);
            if (gy >= 0 && gy < HH && gx >= 0 && gx < WW) {
                v = *reinterpret_cast<const float2*>(
                    &x[(size_t)((b * CI + cc * 32 + c) * HH + gy) * WW + gx]);
            }
            *reinterpret_cast<float2*>(&xs[(c * 7 + i) * XWID + 2 * s2]) = v;
        }
        __syncthreads();

        #pragma unroll
        for (int q = 0; q < 8; q++) {
            int c = cl * 8 + q;          // 0..31
            float acc = 0.f;
            #pragma unroll
            for (int i = 0; i < 7; i++)
                #pragma unroll
                for (int j = 0; j < 7; j++)
                    acc += av[7 * i + j] * xs[(c * 7 + i) * XWID + xc + 2 * j];
            out[(size_t)((b * CI + cc * 32 + c) * HH + y) * WW + xc] = acc;
        }
    }
}

// ---------------------------------------------------------------------------
extern "C" void kernel_launch(void* const* d_in, const int* in_sizes, int n_in,
                              void* d_out, int out_size) {
    const float* x  = (const float*)d_in[0];
    const float* W1 = (const float*)d_in[1];
    const float* b1 = (const float*)d_in[2];
    const float* W2 = (const float*)d_in[3];
    const float* b2 = (const float*)d_in[4];
    float* out = (float*)d_out;
    (void)in_sizes; (void)n_in; (void)out_size;

    k_transpose<<<(CI*KK*CO + 255) / 256, 256>>>(W1);

    dim3 g1(28, 4, BB);
    k_conv1<<<g1, 224>>>(x, b1);

    cudaFuncSetAttribute(k_stage2, cudaFuncAttributeMaxDynamicSharedMemorySize,
                         S2_SMEM);
    dim3 g2(HH, BB);
    k_stage2<<<g2, 224, S2_SMEM>>>(x, W2, b2, out);
}

// round 2
// speedup vs baseline: 1.0839x; 1.0839x over previous
#include <cuda_runtime.h>

#define BB 4
#define CI 256
#define CO 128
#define HH 56
#define WW 56
#define KK 49

typedef unsigned long long u64;

__device__ __forceinline__ u64 bcast2(float v) {
    u64 r;
    asm("mov.b64 %0, {%1, %1};" : "=l"(r) : "f"(v));
    return r;
}
__device__ __forceinline__ void ffma2(u64& acc, u64 a, u64 b) {
    asm("fma.rn.f32x2 %0, %1, %2, %0;" : "+l"(acc) : "l"(a), "l"(b));
}
__device__ __forceinline__ void unpack2(u64 p, float& lo, float& hi) {
    asm("mov.b64 {%0, %1}, %2;" : "=f"(lo), "=f"(hi) : "l"(p));
}

// scratch (static device allocations are allowed)
__device__ float g_O1[BB*CO*HH*WW];          // conv1 output, 6.4 MB
__device__ float g_Wt[CI*KK*CO];             // W1 transposed: [(c*49+t)][m]

// ---------------- kernel 0: transpose W1 [m][c*49+t] -> [c*49+t][m] -------
__global__ void k_transpose(const float* __restrict__ W1) {
    int idx = blockIdx.x * 256 + threadIdx.x;      // over CI*KK*CO
    if (idx >= CI*KK*CO) return;
    int m  = idx & (CO - 1);
    int ct = idx >> 7;
    g_Wt[idx] = W1[m * (CI*KK) + ct];
}

// ---------------- kernel 1: conv1 7x7 dil2 pad6 + bias --------------------
// Block: 32 out-channels x 2 rows x 56 cols. Threads 224 = 8(tc) x 2(tpy) x 14(tpx)
// Thread tile: 4 ch x 4 px, computed as 2 channel-PAIRS x 4 px with fma.rn.f32x2.
#define CC 4
#define MG 32
#define XWID 72   // smem x row width: global cols -6..65 (col = gx+6)

__global__ void __launch_bounds__(224) k_conv1(const float* __restrict__ x,
                                               const float* __restrict__ b1) {
    __shared__ float Xs[CC][14][XWID];     // 16128 B
    __shared__ float Ws[CC][KK][MG];       // 25088 B

    int tid = threadIdx.x;
    int tc  = tid / 28;            // 0..7
    int tpy = (tid % 28) / 14;     // 0..1
    int tpx = tid % 14;            // 0..13

    int rp = blockIdx.x;           // 0..27  row pair
    int mg = blockIdx.y;           // 0..3   channel group of 32
    int b  = blockIdx.z;

    int y0  = rp * 2;
    int y   = y0 + tpy;
    int px0 = tpx * 4;
    int m0  = mg * MG;
    int mt  = m0 + tc * 4;

    // packed accumulators: accp[ap][d] holds out-channels (2ap, 2ap+1) at pixel d
    u64 accp[2][4];
    #pragma unroll
    for (int ap = 0; ap < 2; ap++)
        #pragma unroll
        for (int d = 0; d < 4; d++) accp[ap][d] = 0ull;

    const float* xb = x + (size_t)b * CI * HH * WW;

    for (int cb = 0; cb < CI; cb += CC) {
        __syncthreads();
        // ---- stage X: CC * 14 rows * 34 float2 slots (col = gx+6, gx = 2*s2-6)
        for (int s = tid; s < CC * 14 * 34; s += 224) {
            int c  = s / (14 * 34);
            int rr = (s / 34) % 14;
            int s2 = s % 34;
            int gx = 2 * s2 - 6;
            int gy = y0 - 6 + rr;
            float2 v = make_float2(0.f, 0.f);
            if (gy >= 0 && gy < HH && gx >= 0 && gx < WW) {
                v = *reinterpret_cast<const float2*>(
                        xb + (size_t)(cb + c) * HH * WW + gy * WW + gx);
            }
            *reinterpret_cast<float2*>(&Xs[c][rr][2 * s2]) = v;
        }
        // ---- stage W: CC*49*32 floats as float4, coalesced from g_Wt
        for (int s = tid; s < (CC * KK * MG) / 4; s += 224) {
            int lin = s * 4;
            int c   = lin / (KK * MG);
            int rem = lin % (KK * MG);
            int t   = rem / MG;
            int m   = rem % MG;
            float4 v = *reinterpret_cast<const float4*>(
                &g_Wt[(size_t)((cb + c) * KK + t) * CO + m0 + m]);
            *reinterpret_cast<float4*>(&Ws[c][t][m]) = v;
        }
        __syncthreads();

        #pragma unroll
        for (int c = 0; c < CC; c++) {
            #pragma unroll
            for (int i = 0; i < 7; i++) {
                int rr = tpy + 2 * i;
                // load 16-wide x strip, broadcast each value into a packed pair
                u64 xbc[16];
                #pragma unroll
                for (int q = 0; q < 4; q++) {
                    float4 t4 = *reinterpret_cast<const float4*>(&Xs[c][rr][px0 + 4 * q]);
                    xbc[4*q+0] = bcast2(t4.x); xbc[4*q+1] = bcast2(t4.y);
                    xbc[4*q+2] = bcast2(t4.z); xbc[4*q+3] = bcast2(t4.w);
                }
                #pragma unroll
                for (int j = 0; j < 7; j++) {
                    // w pairs load naturally packed from smem (8B aligned)
                    u64 wp0 = *reinterpret_cast<const u64*>(&Ws[c][7*i+j][tc*4 + 0]);
                    u64 wp1 = *reinterpret_cast<const u64*>(&Ws[c][7*i+j][tc*4 + 2]);
                    #pragma unroll
                    for (int d = 0; d < 4; d++) {
                        ffma2(accp[0][d], wp0, xbc[2*j + d]);
                        ffma2(accp[1][d], wp1, xbc[2*j + d]);
                    }
                }
            }
        }
    }

    // unpack and store with bias
    float acc[4][4];
    #pragma unroll
    for (int ap = 0; ap < 2; ap++)
        #pragma unroll
        for (int d = 0; d < 4; d++)
            unpack2(accp[ap][d], acc[2*ap][d], acc[2*ap+1][d]);

    #pragma unroll
    for (int a = 0; a < 4; a++) {
        float bias = b1[mt + a];
        float4 o;
        o.x = acc[a][0] + bias; o.y = acc[a][1] + bias;
        o.z = acc[a][2] + bias; o.w = acc[a][3] + bias;
        *reinterpret_cast<float4*>(
            &g_O1[(size_t)(((b * CO + mt + a) * HH) + y) * WW + px0]) = o;
    }
}

// ---------------- kernel 2: 1x1 conv -> softmax(49) -> weighted patch sum --
// Block per (b, row y). 224 threads.
// dyn smem: ls[49*56] | region aliased: {O1s[128*56], W2s[49*128]} then xs[32*7*72]
#define S2_LS   (49 * 56)
#define S2_XS   (32 * 7 * 72)
#define S2_SMEM ((S2_LS + S2_XS) * 4)

__global__ void __launch_bounds__(224) k_stage2(const float* __restrict__ x,
                                                const float* __restrict__ W2,
                                                const float* __restrict__ b2,
                                                float* __restrict__ out) {
    extern __shared__ float sm[];
    float* ls  = sm;               // persists whole kernel
    float* O1s = sm + S2_LS;       // phase A only
    float* W2s = O1s + CO * WW;    // phase A only  (O1s+W2s = 13440 fl < 16128)
    float* xs  = sm + S2_LS;       // phase B, aliases O1s/W2s

    int tid = threadIdx.x;
    int y = blockIdx.x;
    int b = blockIdx.y;

    // ---- phase A: load O1 row + W2
    for (int s = tid; s < CO * 14; s += 224) {
        int c = s / 14, q = s % 14;
        float4 v = *reinterpret_cast<const float4*>(
            &g_O1[(size_t)((b * CO + c) * HH + y) * WW + 4 * q]);
        *reinterpret_cast<float4*>(&O1s[c * WW + 4 * q]) = v;
    }
    for (int s = tid; s < (KK * CO) / 4; s += 224) {
        *reinterpret_cast<float4*>(&W2s[4 * s]) =
            *reinterpret_cast<const float4*>(&W2[4 * s]);
    }
    __syncthreads();

    // logits: ls[k][x] = b2[k] + sum_c W2[k][c] * O1[c][x]
    for (int p = tid; p < KK * WW; p += 224) {
        int k = p / WW, xc = p % WW;
        float acc = b2[k];
        #pragma unroll 8
        for (int c = 0; c < CO; c++)
            acc += W2s[k * CO + c] * O1s[c * WW + xc];
        ls[k * WW + xc] = acc;
    }
    __syncthreads();

    // softmax over k (one thread per column)
    if (tid < WW) {
        float mx = -1e30f;
        #pragma unroll
        for (int k = 0; k < KK; k++) mx = fmaxf(mx, ls[k * WW + tid]);
        float s = 0.f;
        #pragma unroll
        for (int k = 0; k < KK; k++) {
            float e = expf(ls[k * WW + tid] - mx);
            ls[k * WW + tid] = e;
            s += e;
        }
        float inv = 1.f / s;
        #pragma unroll
        for (int k = 0; k < KK; k++) ls[k * WW + tid] *= inv;
    }
    __syncthreads();

    // hoist attn to registers
    int cl = tid / WW;     // 0..3
    int xc = tid % WW;     // 0..55
    float av[KK];
    #pragma unroll
    for (int k = 0; k < KK; k++) av[k] = ls[k * WW + xc];

    // ---- phase B: weighted local sum, 8 chunks of 32 channels
    for (int cc = 0; cc < CI / 32; cc++) {
        __syncthreads();
        for (int s = tid; s < 32 * 7 * 34; s += 224) {
            int c  = s / (7 * 34);
            int i  = (s / 34) % 7;
            int s2 = s % 34;
            int gx = 2 * s2 - 6;
            int gy = y - 6 + 2 * i;
            float2 v = make_float2(0.f, 0.f);
            if (gy >= 0 && gy < HH && gx >= 0 && gx < WW) {
                v = *reinterpret_cast<const float2*>(
                    &x[(size_t)((b * CI + cc * 32 + c) * HH + gy) * WW + gx]);
            }
            *reinterpret_cast<float2*>(&xs[(c * 7 + i) * XWID + 2 * s2]) = v;
        }
        __syncthreads();

        #pragma unroll
        for (int q = 0; q < 8; q++) {
            int c = cl * 8 + q;          // 0..31
            float acc = 0.f;
            #pragma unroll
            for (int i = 0; i < 7; i++)
                #pragma unroll
                for (int j = 0; j < 7; j++)
                    acc += av[7 * i + j] * xs[(c * 7 + i) * XWID + xc + 2 * j];
            out[(size_t)((b * CI + cc * 32 + c) * HH + y) * WW + xc] = acc;
        }
    }
}

// ---------------------------------------------------------------------------
extern "C" void kernel_launch(void* const* d_in, const int* in_sizes, int n_in,
                              void* d_out, int out_size) {
    const float* x  = (const float*)d_in[0];
    const float* W1 = (const float*)d_in[1];
    const float* b1 = (const float*)d_in[2];
    const float* W2 = (const float*)d_in[3];
    const float* b2 = (const float*)d_in[4];
    float* out = (float*)d_out;
    (void)in_sizes; (void)n_in; (void)out_size;

    k_transpose<<<(CI*KK*CO + 255) / 256, 256>>>(W1);

    dim3 g1(28, 4, BB);
    k_conv1<<<g1, 224>>>(x, b1);

    cudaFuncSetAttribute(k_stage2, cudaFuncAttributeMaxDynamicSharedMemorySize,
                         S2_SMEM);
    dim3 g2(HH, BB);
    k_stage2<<<g2, 224, S2_SMEM>>>(x, W2, b2, out);
}

// round 4
// speedup vs baseline: 1.1623x; 1.0723x over previous
#include <cuda_runtime.h>
#include <cuda_bf16.h>
#include <cstdint>

#define BB 4
#define CI 256
#define CO 128
#define HH 56
#define WW 56
#define KK 49
#define KTOT (CI*KK)          // 12544
#define KC   64               // K per chunk
#define NCHUNK (KTOT/KC)      // 196
#define NT   112              // N tile: 2 rows x 56 px
#define PXW  72               // padded x row width (bf16 elems)

typedef unsigned int u32;
typedef unsigned long long u64;

// ---------------- device scratch -------------------------------------------
__device__ __align__(16) __nv_bfloat16 g_Ah[NCHUNK*CO*KC];   // pre-swizzled W hi
__device__ __align__(16) __nv_bfloat16 g_Al[NCHUNK*CO*KC];   // pre-swizzled W lo
__device__ __align__(16) __nv_bfloat16 g_xh[BB*CI*HH*PXW];   // padded x hi
__device__ __align__(16) __nv_bfloat16 g_xl[BB*CI*HH*PXW];   // padded x lo
__device__ float g_O1[BB*CO*HH*WW];

#define SWZ(o) ((o) ^ (((o) >> 3) & 0x70))

// ---------------- PTX helpers (all baseline ISA, sm_80+) -------------------
__device__ __forceinline__ u32 smem_u32(const void* p) {
    u32 a;
    asm("{ .reg .u64 t; cvta.to.shared.u64 t, %1; cvt.u32.u64 %0, t; }"
        : "=r"(a) : "l"(p));
    return a;
}
__device__ __forceinline__ void cpasync16(u32 dst, const void* src, u32 srcsize) {
    u64 gsrc = (u64)__cvta_generic_to_global(src);
    asm volatile("cp.async.cg.shared.global [%0], [%1], 16, %2;"
                 :: "r"(dst), "l"(gsrc), "r"(srcsize) : "memory");
}
#define CP_COMMIT() asm volatile("cp.async.commit_group;" ::: "memory")
#define CP_WAIT0()  asm volatile("cp.async.wait_group 0;" ::: "memory")

__device__ __forceinline__ void ldm_x4(u32* r, u32 addr) {
    asm volatile("ldmatrix.sync.aligned.m8n8.x4.shared.b16 {%0,%1,%2,%3}, [%4];"
        : "=r"(r[0]), "=r"(r[1]), "=r"(r[2]), "=r"(r[3]) : "r"(addr));
}
__device__ __forceinline__ void ldm_x2(u32* r, u32 addr) {
    asm volatile("ldmatrix.sync.aligned.m8n8.x2.shared.b16 {%0,%1}, [%2];"
        : "=r"(r[0]), "=r"(r[1]) : "r"(addr));
}
__device__ __forceinline__ void mma16816(float* c, const u32* a, const u32* b) {
    asm volatile("mma.sync.aligned.m16n8k16.row.col.f32.bf16.bf16.f32 "
        "{%0,%1,%2,%3}, {%4,%5,%6,%7}, {%8,%9}, {%0,%1,%2,%3};"
        : "+f"(c[0]), "+f"(c[1]), "+f"(c[2]), "+f"(c[3])
        : "r"(a[0]), "r"(a[1]), "r"(a[2]), "r"(a[3]), "r"(b[0]), "r"(b[1]));
}

// ---------------- prep: W1 -> bf16 hi/lo, pre-swizzled per-chunk tiles -----
__global__ void k_prepw(const float* __restrict__ W1) {
    int q = blockIdx.x;          // chunk
    int m = threadIdx.x;         // out-channel
    const float* src = W1 + (size_t)m * KTOT + q * KC;
    __align__(16) __nv_bfloat16 hb[KC], lb[KC];
    #pragma unroll
    for (int kk = 0; kk < KC; kk++) {
        float v = src[kk];
        __nv_bfloat16 h = __float2bfloat16(v);
        hb[kk] = h;
        lb[kk] = __float2bfloat16(v - __bfloat162float(h));
    }
    char* dh = (char*)g_Ah + (size_t)q * CO * KC * 2;
    char* dl = (char*)g_Al + (size_t)q * CO * KC * 2;
    #pragma unroll
    for (int g = 0; g < 8; g++) {
        unsigned off = SWZ((unsigned)(m * 128 + g * 16));
        *(uint4*)(dh + off) = *(uint4*)&hb[g * 8];
        *(uint4*)(dl + off) = *(uint4*)&lb[g * 8];
    }
}

// ---------------- prep: x -> padded bf16 hi/lo planes ----------------------
__global__ void k_prepx(const float* __restrict__ x) {
    int idx = blockIdx.x * 128 + threadIdx.x;   // over BB*CI*HH rows
    if (idx >= BB * CI * HH) return;
    const float* row = x + (size_t)idx * WW;
    __align__(16) __nv_bfloat16 h[PXW], l[PXW];
    #pragma unroll
    for (int i = 0; i < PXW; i++) {
        int gx = i - 6;
        float v = (gx >= 0 && gx < WW) ? row[gx] : 0.f;
        __nv_bfloat16 hh = __float2bfloat16(v);
        h[i] = hh;
        l[i] = __float2bfloat16(v - __bfloat162float(hh));
    }
    uint4* dh = (uint4*)((char*)g_xh + (size_t)idx * PXW * 2);
    uint4* dl = (uint4*)((char*)g_xl + (size_t)idx * PXW * 2);
    #pragma unroll
    for (int s = 0; s < 9; s++) { dh[s] = ((uint4*)h)[s]; dl[s] = ((uint4*)l)[s]; }
}

// ---------------- conv1: mma.sync implicit GEMM ----------------------------
#define TILE_A 16384              // 128 rows * 128B
#define TILE_B 14336              // 112 rows * 128B
#define XS_SZ  12096              // 84 rows * 144B
#define SM_XS  0
#define SM_A   (2*XS_SZ)          // 24192
#define SM_B   (SM_A + 4*TILE_A)  // 89728
#define SM_TOTAL (SM_B + 2*TILE_B) // 118400

__global__ void __launch_bounds__(256, 1) k_conv1(const float* __restrict__ b1) {
    extern __shared__ char smem[];
    u32 sb = smem_u32(smem);
    int tid = threadIdx.x, wid = tid >> 5, lane = tid & 31;
    int rp = blockIdx.x, b = blockIdx.y;
    int y0 = rp * 2;
    int wm = wid & 3, wn = wid >> 2;

    // B-gather identity (224 active threads)
    int gact = (tid < 224);
    int gterm = tid / 112, gn = tid % 112;
    int gdy = gn / 56, gxn = gn % 56;

    float acc[56];
    #pragma unroll
    for (int i = 0; i < 56; i++) acc[i] = 0.f;

    auto stage = [&](int q, int p) {
        int c0 = (q * KC) / KK;
        // xs: 84 rows (2 terms * 3 ch * 14 rows) x 9 segs of 16B
        for (int s = tid; s < 756; s += 256) {
            int rowi = s / 9, seg = s % 9;
            int trm = rowi / 42, rem = rowi % 42, cc = rem / 14, r = rem % 14;
            int cp = c0 + cc, gy = y0 - 6 + r;
            bool v = (gy >= 0 && gy < HH && cp < CI);
            const char* base = trm ? (const char*)g_xl : (const char*)g_xh;
            const char* src = base +
                ((size_t)((b * CI + (v ? cp : 0)) * HH + (v ? gy : 0)) * PXW) * 2 + seg * 16;
            u32 dst = sb + SM_XS + p * XS_SZ + ((trm * 3 + cc) * 14 + r) * 144 + seg * 16;
            cpasync16(dst, src, v ? 16u : 0u);
        }
        // A tiles: 2 terms x 1024 segs of 16B (pre-swizzled in gmem)
        const char* gah = (const char*)g_Ah + (size_t)q * TILE_A;
        const char* gal = (const char*)g_Al + (size_t)q * TILE_A;
        for (int s = tid; s < 2048; s += 256) {
            int trm = s >> 10, seg = s & 1023;
            const char* src = (trm ? gal : gah) + seg * 16;
            cpasync16(sb + SM_A + p * (2 * TILE_A) + trm * TILE_A + seg * 16, src, 16u);
        }
    };

    stage(0, 0); CP_COMMIT();

    // ldmatrix per-lane bases (SW128 swizzle = xor (row%8)<<4 on the column)
    u32 xorm  = (u32)(lane & 7) << 4;
    u32 aRow  = (u32)(wm * 32 + (lane & 15)) * 128;
    u32 aCol  = (u32)(lane >> 4) * 16;
    u32 bRow4 = (u32)(wn * 56 + ((lane >> 4) << 3) + (lane & 7)) * 128;
    u32 bRow2 = (u32)(wn * 56 + 48 + (lane & 7)) * 128;
    u32 bCol  = (u32)((lane >> 3) & 1) * 16;

    for (int q = 0; q < NCHUNK; q++) {
        int p = q & 1;
        CP_WAIT0();
        __syncthreads();
        if (q + 1 < NCHUNK) { stage(q + 1, p ^ 1); CP_COMMIT(); }

        // ---- build B tiles (im2col gather from xs[p])
        if (gact) {
            int k0 = q * KC, c0 = k0 / KK, t0 = k0 - KK * c0;
            int tj = t0 % 7;
            const char* xsrc = smem + SM_XS + p * XS_SZ + gterm * 6048;
            int idx = (gdy + 2 * (t0 / 7)) * PXW + gxn + 2 * tj;
            char* Bt = smem + SM_B + gterm * TILE_B;
            u32 rowoff = (u32)(gn * 128);
            #pragma unroll
            for (int g = 0; g < 8; g++) {
                u32 v[4];
                #pragma unroll
                for (int h2 = 0; h2 < 4; h2++) {
                    u32 a = *(const unsigned short*)(xsrc + idx * 2);
                    idx += (tj == 6) ? 132 : 2; tj = (tj == 6) ? 0 : tj + 1;
                    u32 bb = *(const unsigned short*)(xsrc + idx * 2);
                    idx += (tj == 6) ? 132 : 2; tj = (tj == 6) ? 0 : tj + 1;
                    v[h2] = a | (bb << 16);
                }
                *(uint4*)(Bt + SWZ(rowoff + g * 16)) = *(uint4*)v;
            }
        }
        __syncthreads();

        // ---- 3-term MMA over this chunk (4 k16-steps)
        u32 Ah = sb + SM_A + p * (2 * TILE_A);
        u32 Al = Ah + TILE_A;
        u32 Bh = sb + SM_B;
        u32 Bl = Bh + TILE_B;

        #pragma unroll
        for (int ks = 0; ks < 4; ks++) {
            u32 colA = ((u32)(ks * 32) + aCol) ^ xorm;
            u32 colB = ((u32)(ks * 32) + bCol) ^ xorm;
            u32 bh[14], bl[14];
            #pragma unroll
            for (int pp = 0; pp < 3; pp++) {
                ldm_x4(&bh[4 * pp], Bh + bRow4 + pp * 2048 + colB);
                ldm_x4(&bl[4 * pp], Bl + bRow4 + pp * 2048 + colB);
            }
            ldm_x2(&bh[12], Bh + bRow2 + colB);
            ldm_x2(&bl[12], Bl + bRow2 + colB);
            #pragma unroll
            for (int mf = 0; mf < 2; mf++) {
                u32 ah[4], al[4];
                ldm_x4(ah, Ah + aRow + mf * 2048 + colA);
                ldm_x4(al, Al + aRow + mf * 2048 + colA);
                #pragma unroll
                for (int nf = 0; nf < 7; nf++) {
                    float* c = &acc[(mf * 7 + nf) * 4];
                    mma16816(c, ah, &bh[2 * nf]);
                    mma16816(c, ah, &bl[2 * nf]);
                    mma16816(c, al, &bh[2 * nf]);
                }
            }
        }
    }

    // ---- epilogue: registers -> g_O1 with bias
    int yy = y0 + wn;
    #pragma unroll
    for (int mf = 0; mf < 2; mf++) {
        int m = wm * 32 + mf * 16 + (lane >> 2);
        float bia0 = b1[m], bia8 = b1[m + 8];
        float* r0 = g_O1 + (size_t)((b * CO + m) * HH + yy) * WW;
        float* r8 = g_O1 + (size_t)((b * CO + m + 8) * HH + yy) * WW;
        #pragma unroll
        for (int nf = 0; nf < 7; nf++) {
            float* c = &acc[(mf * 7 + nf) * 4];
            int xx = nf * 8 + 2 * (lane & 3);
            *(float2*)(r0 + xx) = make_float2(c[0] + bia0, c[1] + bia0);
            *(float2*)(r8 + xx) = make_float2(c[2] + bia8, c[3] + bia8);
        }
    }
}

// ---------------- kernel 2: 1x1 conv -> softmax(49) -> weighted patch sum --
#define S2_LS   (49 * 56)
#define S2_XS   (32 * 7 * 72)
#define S2_SMEM ((S2_LS + S2_XS) * 4)
#define XWID 72

__global__ void __launch_bounds__(224) k_stage2(const float* __restrict__ x,
                                                const float* __restrict__ W2,
                                                const float* __restrict__ b2,
                                                float* __restrict__ out) {
    extern __shared__ float sm[];
    float* ls  = sm;
    float* O1s = sm + S2_LS;
    float* W2s = O1s + CO * WW;
    float* xs  = sm + S2_LS;

    int tid = threadIdx.x;
    int y = blockIdx.x;
    int b = blockIdx.y;

    for (int s = tid; s < CO * 14; s += 224) {
        int c = s / 14, qq = s % 14;
        float4 v = *reinterpret_cast<const float4*>(
            &g_O1[(size_t)((b * CO + c) * HH + y) * WW + 4 * qq]);
        *reinterpret_cast<float4*>(&O1s[c * WW + 4 * qq]) = v;
    }
    for (int s = tid; s < (KK * CO) / 4; s += 224) {
        *reinterpret_cast<float4*>(&W2s[4 * s]) =
            *reinterpret_cast<const float4*>(&W2[4 * s]);
    }
    __syncthreads();

    for (int p = tid; p < KK * WW; p += 224) {
        int k = p / WW, xc = p % WW;
        float acc = b2[k];
        #pragma unroll 8
        for (int c = 0; c < CO; c++)
            acc += W2s[k * CO + c] * O1s[c * WW + xc];
        ls[k * WW + xc] = acc;
    }
    __syncthreads();

    if (tid < WW) {
        float mx = -1e30f;
        #pragma unroll
        for (int k = 0; k < KK; k++) mx = fmaxf(mx, ls[k * WW + tid]);
        float s = 0.f;
        #pragma unroll
        for (int k = 0; k < KK; k++) {
            float e = expf(ls[k * WW + tid] - mx);
            ls[k * WW + tid] = e;
            s += e;
        }
        float inv = 1.f / s;
        #pragma unroll
        for (int k = 0; k < KK; k++) ls[k * WW + tid] *= inv;
    }
    __syncthreads();

    int cl = tid / WW;
    int xc = tid % WW;
    float av[KK];
    #pragma unroll
    for (int k = 0; k < KK; k++) av[k] = ls[k * WW + xc];

    for (int cc = 0; cc < CI / 32; cc++) {
        __syncthreads();
        for (int s = tid; s < 32 * 7 * 34; s += 224) {
            int c  = s / (7 * 34);
            int i  = (s / 34) % 7;
            int s2 = s % 34;
            int gx = 2 * s2 - 6;
            int gy = y - 6 + 2 * i;
            float2 v = make_float2(0.f, 0.f);
            if (gy >= 0 && gy < HH && gx >= 0 && gx < WW) {
                v = *reinterpret_cast<const float2*>(
                    &x[(size_t)((b * CI + cc * 32 + c) * HH + gy) * WW + gx]);
            }
            *reinterpret_cast<float2*>(&xs[(c * 7 + i) * XWID + 2 * s2]) = v;
        }
        __syncthreads();

        #pragma unroll
        for (int qq = 0; qq < 8; qq++) {
            int c = cl * 8 + qq;
            float acc = 0.f;
            #pragma unroll
            for (int i = 0; i < 7; i++)
                #pragma unroll
                for (int j = 0; j < 7; j++)
                    acc += av[7 * i + j] * xs[(c * 7 + i) * XWID + xc + 2 * j];
            out[(size_t)((b * CI + cc * 32 + c) * HH + y) * WW + xc] = acc;
        }
    }
}

// ---------------------------------------------------------------------------
extern "C" void kernel_launch(void* const* d_in, const int* in_sizes, int n_in,
                              void* d_out, int out_size) {
    const float* x  = (const float*)d_in[0];
    const float* W1 = (const float*)d_in[1];
    const float* b1 = (const float*)d_in[2];
    const float* W2 = (const float*)d_in[3];
    const float* b2 = (const float*)d_in[4];
    float* out = (float*)d_out;
    (void)in_sizes; (void)n_in; (void)out_size;

    k_prepw<<<NCHUNK, 128>>>(W1);
    k_prepx<<<(BB * CI * HH + 127) / 128, 128>>>(x);

    cudaFuncSetAttribute(k_conv1, cudaFuncAttributeMaxDynamicSharedMemorySize,
                         SM_TOTAL);
    dim3 g1(28, BB);
    k_conv1<<<g1, 256, SM_TOTAL>>>(b1);

    cudaFuncSetAttribute(k_stage2, cudaFuncAttributeMaxDynamicSharedMemorySize,
                         S2_SMEM);
    dim3 g2(HH, BB);
    k_stage2<<<g2, 224, S2_SMEM>>>(x, W2, b2, out);
}

// round 5
// speedup vs baseline: 1.8154x; 1.5620x over previous
#include <cuda_runtime.h>
#include <cuda_bf16.h>
#include <cstdint>

#define BB 4
#define CI 256
#define CO 128
#define HH 56
#define WW 56
#define KK 49
#define KTOT (CI*KK)          // 12544
#define KC   64               // K per chunk
#define NCHUNK (KTOT/KC)      // 196
#define NT   112              // N tile: 2 rows x 56 px
#define PXW  72               // padded x row width (bf16 elems)

typedef unsigned int u32;
typedef unsigned long long u64;

// ---------------- device scratch -------------------------------------------
__device__ __align__(16) __nv_bfloat16 g_Ah[NCHUNK*CO*KC];   // pre-swizzled W hi
__device__ __align__(16) __nv_bfloat16 g_Al[NCHUNK*CO*KC];   // pre-swizzled W lo
__device__ __align__(16) __nv_bfloat16 g_xh[BB*CI*HH*PXW];   // padded x hi
__device__ __align__(16) __nv_bfloat16 g_xl[BB*CI*HH*PXW];   // padded x lo
__device__ float g_O1[BB*CO*HH*WW];

#define SWZ(o) ((o) ^ (((o) >> 3) & 0x70))

// ---------------- PTX helpers (all baseline ISA, sm_80+) -------------------
__device__ __forceinline__ u32 smem_u32(const void* p) {
    u32 a;
    asm("{ .reg .u64 t; cvta.to.shared.u64 t, %1; cvt.u32.u64 %0, t; }"
        : "=r"(a) : "l"(p));
    return a;
}
__device__ __forceinline__ void cpasync16(u32 dst, const void* src, u32 srcsize) {
    u64 gsrc = (u64)__cvta_generic_to_global(src);
    asm volatile("cp.async.cg.shared.global [%0], [%1], 16, %2;"
                 :: "r"(dst), "l"(gsrc), "r"(srcsize) : "memory");
}
#define CP_COMMIT() asm volatile("cp.async.commit_group;" ::: "memory")
#define CP_WAIT0()  asm volatile("cp.async.wait_group 0;" ::: "memory")

__device__ __forceinline__ void ldm_x4(u32* r, u32 addr) {
    asm volatile("ldmatrix.sync.aligned.m8n8.x4.shared.b16 {%0,%1,%2,%3}, [%4];"
        : "=r"(r[0]), "=r"(r[1]), "=r"(r[2]), "=r"(r[3]) : "r"(addr));
}
__device__ __forceinline__ void ldm_x2(u32* r, u32 addr) {
    asm volatile("ldmatrix.sync.aligned.m8n8.x2.shared.b16 {%0,%1}, [%2];"
        : "=r"(r[0]), "=r"(r[1]) : "r"(addr));
}
__device__ __forceinline__ void mma16816(float* c, const u32* a, const u32* b) {
    asm volatile("mma.sync.aligned.m16n8k16.row.col.f32.bf16.bf16.f32 "
        "{%0,%1,%2,%3}, {%4,%5,%6,%7}, {%8,%9}, {%0,%1,%2,%3};"
        : "+f"(c[0]), "+f"(c[1]), "+f"(c[2]), "+f"(c[3])
        : "r"(a[0]), "r"(a[1]), "r"(a[2]), "r"(a[3]), "r"(b[0]), "r"(b[1]));
}

// ---------------- prep: W1 -> bf16 hi/lo, pre-swizzled per-chunk tiles -----
__global__ void k_prepw(const float* __restrict__ W1) {
    int q = blockIdx.x;          // chunk
    int m = threadIdx.x;         // out-channel
    const float* src = W1 + (size_t)m * KTOT + q * KC;
    __align__(16) __nv_bfloat16 hb[KC], lb[KC];
    #pragma unroll
    for (int kk = 0; kk < KC; kk++) {
        float v = src[kk];
        __nv_bfloat16 h = __float2bfloat16(v);
        hb[kk] = h;
        lb[kk] = __float2bfloat16(v - __bfloat162float(h));
    }
    char* dh = (char*)g_Ah + (size_t)q * CO * KC * 2;
    char* dl = (char*)g_Al + (size_t)q * CO * KC * 2;
    #pragma unroll
    for (int g = 0; g < 8; g++) {
        unsigned off = SWZ((unsigned)(m * 128 + g * 16));
        *(uint4*)(dh + off) = *(uint4*)&hb[g * 8];
        *(uint4*)(dl + off) = *(uint4*)&lb[g * 8];
    }
}

// ---------------- prep: x -> padded bf16 hi/lo planes ----------------------
__global__ void k_prepx(const float* __restrict__ x) {
    int idx = blockIdx.x * 128 + threadIdx.x;   // over BB*CI*HH rows
    if (idx >= BB * CI * HH) return;
    const float* row = x + (size_t)idx * WW;
    __align__(16) __nv_bfloat16 h[PXW], l[PXW];
    #pragma unroll
    for (int i = 0; i < PXW; i++) {
        int gx = i - 6;
        float v = (gx >= 0 && gx < WW) ? row[gx] : 0.f;
        __nv_bfloat16 hh = __float2bfloat16(v);
        h[i] = hh;
        l[i] = __float2bfloat16(v - __bfloat162float(hh));
    }
    uint4* dh = (uint4*)((char*)g_xh + (size_t)idx * PXW * 2);
    uint4* dl = (uint4*)((char*)g_xl + (size_t)idx * PXW * 2);
    #pragma unroll
    for (int s = 0; s < 9; s++) { dh[s] = ((uint4*)h)[s]; dl[s] = ((uint4*)l)[s]; }
}

// ---------------- conv1: mma.sync implicit GEMM ----------------------------
#define TILE_A 16384              // 128 rows * 128B
#define TILE_B 14336              // 112 rows * 128B
#define XS_SZ  12096              // 84 rows * 144B
#define SM_XS  0
#define SM_A   (2*XS_SZ)          // 24192
#define SM_B   (SM_A + 4*TILE_A)  // 89728
#define SM_TOTAL (SM_B + 2*TILE_B) // 118400

__global__ void __launch_bounds__(256, 1) k_conv1(const float* __restrict__ b1) {
    extern __shared__ char smem[];
    u32 sb = smem_u32(smem);
    int tid = threadIdx.x, wid = tid >> 5, lane = tid & 31;
    int rp = blockIdx.x, b = blockIdx.y;
    int y0 = rp * 2;
    int wm = wid & 3, wn = wid >> 2;

    // B-gather identity (224 active threads)
    int gact = (tid < 224);
    int gterm = tid / 112, gn = tid % 112;
    int gdy = gn / 56, gxn = gn % 56;

    float acc[56];
    #pragma unroll
    for (int i = 0; i < 56; i++) acc[i] = 0.f;

    auto stage = [&](int q, int p) {
        int c0 = (q * KC) / KK;
        // xs: 84 rows (2 terms * 3 ch * 14 rows) x 9 segs of 16B
        for (int s = tid; s < 756; s += 256) {
            int rowi = s / 9, seg = s % 9;
            int trm = rowi / 42, rem = rowi % 42, cc = rem / 14, r = rem % 14;
            int cp = c0 + cc, gy = y0 - 6 + r;
            bool v = (gy >= 0 && gy < HH && cp < CI);
            const char* base = trm ? (const char*)g_xl : (const char*)g_xh;
            const char* src = base +
                ((size_t)((b * CI + (v ? cp : 0)) * HH + (v ? gy : 0)) * PXW) * 2 + seg * 16;
            u32 dst = sb + SM_XS + p * XS_SZ + ((trm * 3 + cc) * 14 + r) * 144 + seg * 16;
            cpasync16(dst, src, v ? 16u : 0u);
        }
        // A tiles: 2 terms x 1024 segs of 16B (pre-swizzled in gmem)
        const char* gah = (const char*)g_Ah + (size_t)q * TILE_A;
        const char* gal = (const char*)g_Al + (size_t)q * TILE_A;
        for (int s = tid; s < 2048; s += 256) {
            int trm = s >> 10, seg = s & 1023;
            const char* src = (trm ? gal : gah) + seg * 16;
            cpasync16(sb + SM_A + p * (2 * TILE_A) + trm * TILE_A + seg * 16, src, 16u);
        }
    };

    stage(0, 0); CP_COMMIT();

    // ldmatrix per-lane bases (SW128 swizzle = xor (row%8)<<4 on the column)
    u32 xorm  = (u32)(lane & 7) << 4;
    u32 aRow  = (u32)(wm * 32 + (lane & 15)) * 128;
    u32 aCol  = (u32)(lane >> 4) * 16;
    u32 bRow4 = (u32)(wn * 56 + ((lane >> 4) << 3) + (lane & 7)) * 128;
    u32 bRow2 = (u32)(wn * 56 + 48 + (lane & 7)) * 128;
    u32 bCol  = (u32)((lane >> 3) & 1) * 16;

    for (int q = 0; q < NCHUNK; q++) {
        int p = q & 1;
        CP_WAIT0();
        __syncthreads();
        if (q + 1 < NCHUNK) { stage(q + 1, p ^ 1); CP_COMMIT(); }

        // ---- build B tiles (im2col gather from xs[p])
        if (gact) {
            int k0 = q * KC, c0 = k0 / KK, t0 = k0 - KK * c0;
            int tj = t0 % 7;
            const char* xsrc = smem + SM_XS + p * XS_SZ + gterm * 6048;
            int idx = (gdy + 2 * (t0 / 7)) * PXW + gxn + 2 * tj;
            char* Bt = smem + SM_B + gterm * TILE_B;
            u32 rowoff = (u32)(gn * 128);
            #pragma unroll
            for (int g = 0; g < 8; g++) {
                u32 v[4];
                #pragma unroll
                for (int h2 = 0; h2 < 4; h2++) {
                    u32 a = *(const unsigned short*)(xsrc + idx * 2);
                    idx += (tj == 6) ? 132 : 2; tj = (tj == 6) ? 0 : tj + 1;
                    u32 bb = *(const unsigned short*)(xsrc + idx * 2);
                    idx += (tj == 6) ? 132 : 2; tj = (tj == 6) ? 0 : tj + 1;
                    v[h2] = a | (bb << 16);
                }
                *(uint4*)(Bt + SWZ(rowoff + g * 16)) = *(uint4*)v;
            }
        }
        __syncthreads();

        // ---- 3-term MMA over this chunk (4 k16-steps)
        u32 Ah = sb + SM_A + p * (2 * TILE_A);
        u32 Al = Ah + TILE_A;
        u32 Bh = sb + SM_B;
        u32 Bl = Bh + TILE_B;

        #pragma unroll
        for (int ks = 0; ks < 4; ks++) {
            u32 colA = ((u32)(ks * 32) + aCol) ^ xorm;
            u32 colB = ((u32)(ks * 32) + bCol) ^ xorm;
            u32 bh[14], bl[14];
            #pragma unroll
            for (int pp = 0; pp < 3; pp++) {
                ldm_x4(&bh[4 * pp], Bh + bRow4 + pp * 2048 + colB);
                ldm_x4(&bl[4 * pp], Bl + bRow4 + pp * 2048 + colB);
            }
            ldm_x2(&bh[12], Bh + bRow2 + colB);
            ldm_x2(&bl[12], Bl + bRow2 + colB);
            #pragma unroll
            for (int mf = 0; mf < 2; mf++) {
                u32 ah[4], al[4];
                ldm_x4(ah, Ah + aRow + mf * 2048 + colA);
                ldm_x4(al, Al + aRow + mf * 2048 + colA);
                #pragma unroll
                for (int nf = 0; nf < 7; nf++) {
                    float* c = &acc[(mf * 7 + nf) * 4];
                    mma16816(c, ah, &bh[2 * nf]);
                    mma16816(c, ah, &bl[2 * nf]);
                    mma16816(c, al, &bh[2 * nf]);
                }
            }
        }
    }

    // ---- epilogue: registers -> g_O1 with bias
    int yy = y0 + wn;
    #pragma unroll
    for (int mf = 0; mf < 2; mf++) {
        int m = wm * 32 + mf * 16 + (lane >> 2);
        float bia0 = b1[m], bia8 = b1[m + 8];
        float* r0 = g_O1 + (size_t)((b * CO + m) * HH + yy) * WW;
        float* r8 = g_O1 + (size_t)((b * CO + m + 8) * HH + yy) * WW;
        #pragma unroll
        for (int nf = 0; nf < 7; nf++) {
            float* c = &acc[(mf * 7 + nf) * 4];
            int xx = nf * 8 + 2 * (lane & 3);
            *(float2*)(r0 + xx) = make_float2(c[0] + bia0, c[1] + bia0);
            *(float2*)(r8 + xx) = make_float2(c[2] + bia8, c[3] + bia8);
        }
    }
}

// ---------------- kernel 2: 1x1 conv -> softmax(49) -> weighted patch sum --
#define S2_LS   (49 * 56)
#define S2_XS   (32 * 7 * 72)
#define S2_SMEM ((S2_LS + S2_XS) * 4)
#define XWID 72

__global__ void __launch_bounds__(224) k_stage2(const float* __restrict__ x,
                                                const float* __restrict__ W2,
                                                const float* __restrict__ b2,
                                                float* __restrict__ out) {
    extern __shared__ float sm[];
    float* ls  = sm;
    float* O1s = sm + S2_LS;
    float* W2s = O1s + CO * WW;
    float* xs  = sm + S2_LS;

    int tid = threadIdx.x;
    int y = blockIdx.x;
    int b = blockIdx.y;

    for (int s = tid; s < CO * 14; s += 224) {
        int c = s / 14, qq = s % 14;
        float4 v = *reinterpret_cast<const float4*>(
            &g_O1[(size_t)((b * CO + c) * HH + y) * WW + 4 * qq]);
        *reinterpret_cast<float4*>(&O1s[c * WW + 4 * qq]) = v;
    }
    for (int s = tid; s < (KK * CO) / 4; s += 224) {
        *reinterpret_cast<float4*>(&W2s[4 * s]) =
            *reinterpret_cast<const float4*>(&W2[4 * s]);
    }
    __syncthreads();

    for (int p = tid; p < KK * WW; p += 224) {
        int k = p / WW, xc = p % WW;
        float acc = b2[k];
        #pragma unroll 8
        for (int c = 0; c < CO; c++)
            acc += W2s[k * CO + c] * O1s[c * WW + xc];
        ls[k * WW + xc] = acc;
    }
    __syncthreads();

    if (tid < WW) {
        float mx = -1e30f;
        #pragma unroll
        for (int k = 0; k < KK; k++) mx = fmaxf(mx, ls[k * WW + tid]);
        float s = 0.f;
        #pragma unroll
        for (int k = 0; k < KK; k++) {
            float e = expf(ls[k * WW + tid] - mx);
            ls[k * WW + tid] = e;
            s += e;
        }
        float inv = 1.f / s;
        #pragma unroll
        for (int k = 0; k < KK; k++) ls[k * WW + tid] *= inv;
    }
    __syncthreads();

    int cl = tid / WW;
    int xc = tid % WW;
    float av[KK];
    #pragma unroll
    for (int k = 0; k < KK; k++) av[k] = ls[k * WW + xc];

    for (int cc = 0; cc < CI / 32; cc++) {
        __syncthreads();
        for (int s = tid; s < 32 * 7 * 34; s += 224) {
            int c  = s / (7 * 34);
            int i  = (s / 34) % 7;
            int s2 = s % 34;
            int gx = 2 * s2 - 6;
            int gy = y - 6 + 2 * i;
            float2 v = make_float2(0.f, 0.f);
            if (gy >= 0 && gy < HH && gx >= 0 && gx < WW) {
                v = *reinterpret_cast<const float2*>(
                    &x[(size_t)((b * CI + cc * 32 + c) * HH + gy) * WW + gx]);
            }
            *reinterpret_cast<float2*>(&xs[(c * 7 + i) * XWID + 2 * s2]) = v;
        }
        __syncthreads();

        #pragma unroll
        for (int qq = 0; qq < 8; qq++) {
            int c = cl * 8 + qq;
            float acc = 0.f;
            #pragma unroll
            for (int i = 0; i < 7; i++)
                #pragma unroll
                for (int j = 0; j < 7; j++)
                    acc += av[7 * i + j] * xs[(c * 7 + i) * XWID + xc + 2 * j];
            out[(size_t)((b * CI + cc * 32 + c) * HH + y) * WW + xc] = acc;
        }
    }
}

// ---------------------------------------------------------------------------
extern "C" void kernel_launch(void* const* d_in, const int* in_sizes, int n_in,
                              void* d_out, int out_size) {
    const float* x  = (const float*)d_in[0];
    const float* W1 = (const float*)d_in[1];
    const float* b1 = (const float*)d_in[2];
    const float* W2 = (const float*)d_in[3];
    const float* b2 = (const float*)d_in[4];
    float* out = (float*)d_out;
    (void)in_sizes; (void)n_in; (void)out_size;

    k_prepw<<<NCHUNK, 128>>>(W1);
    k_prepx<<<(BB * CI * HH + 127) / 128, 128>>>(x);

    cudaFuncSetAttribute(k_conv1, cudaFuncAttributeMaxDynamicSharedMemorySize,
                         SM_TOTAL);
    dim3 g1(28, BB);
    k_conv1<<<g1, 256, SM_TOTAL>>>(b1);

    cudaFuncSetAttribute(k_stage2, cudaFuncAttributeMaxDynamicSharedMemorySize,
                         S2_SMEM);
    dim3 g2(HH, BB);
    k_stage2<<<g2, 224, S2_SMEM>>>(x, W2, b2, out);
}